// round 1
// baseline (speedup 1.0000x reference)
#include <cuda_runtime.h>
#include <cuda_bf16.h>
#include <cstdint>

#define HNUM 8
#define NSEQ 4096
#define FIN  512
#define HD   64

// ---------------- scratch (static device globals; no allocations) ----------
__device__ float g_Q[HNUM * NSEQ * HD];
__device__ float g_K[HNUM * NSEQ * HD];
__device__ float g_V[HNUM * NSEQ * HD];
__device__ float g_Hcat[NSEQ * FIN];

// ---------------- helpers --------------------------------------------------
__device__ __forceinline__ uint32_t pack_bf16x2(float lo_elem, float hi_elem) {
    return (uint32_t)__bfloat16_as_ushort(__float2bfloat16_rn(lo_elem)) |
           ((uint32_t)__bfloat16_as_ushort(__float2bfloat16_rn(hi_elem)) << 16);
}

// split a pair of floats into bf16 hi and bf16 lo (x = hi + lo to ~2^-18)
__device__ __forceinline__ void split2(float a, float b, uint32_t& hi, uint32_t& lo) {
    float ah = __bfloat162float(__float2bfloat16_rn(a));
    float bh = __bfloat162float(__float2bfloat16_rn(b));
    hi = pack_bf16x2(a, b);           // rounds identically to ah,bh
    lo = pack_bf16x2(a - ah, b - bh);
}

__device__ __forceinline__ void mma16816(float* c,
                                         uint32_t a0, uint32_t a1, uint32_t a2, uint32_t a3,
                                         uint32_t b0, uint32_t b1) {
    asm volatile(
        "mma.sync.aligned.m16n8k16.row.col.f32.bf16.bf16.f32 "
        "{%0,%1,%2,%3},{%4,%5,%6,%7},{%8,%9},{%0,%1,%2,%3};\n"
        : "+f"(c[0]), "+f"(c[1]), "+f"(c[2]), "+f"(c[3])
        : "r"(a0), "r"(a1), "r"(a2), "r"(a3), "r"(b0), "r"(b1));
}

#define NEG_BIG (-1.0e30f)

// ---------------- generic 128x64 GEMM tile core, C = A[128,512] * B[64,512]^T
// bf16 x3-split for ~fp32 accuracy. 256 threads (8 warps), warp w owns rows 16w..16w+15.
__device__ __forceinline__ void gemm_core(const float* __restrict__ A, int lda,
                                          const float* __restrict__ B, int ldb,
                                          float* __restrict__ C, int ldc) {
    __shared__ __align__(16) uint32_t AsH[128][20];
    __shared__ __align__(16) uint32_t AsL[128][20];
    __shared__ __align__(16) uint32_t BsH[64][20];
    __shared__ __align__(16) uint32_t BsL[64][20];

    const int tid = threadIdx.x;
    const int wid = tid >> 5, lane = tid & 31;
    const int g = lane >> 2, q = lane & 3;

    float acc[8][4];
#pragma unroll
    for (int i = 0; i < 8; i++)
#pragma unroll
        for (int j = 0; j < 4; j++) acc[i][j] = 0.f;

    for (int kc = 0; kc < FIN; kc += 32) {
        // A tile: 128x32 floats = 1024 float4
#pragma unroll
        for (int j = 0; j < 4; j++) {
            int idx = tid + j * 256;
            int r = idx >> 3, c4 = (idx & 7) << 2;
            float4 v = *reinterpret_cast<const float4*>(A + (size_t)r * lda + kc + c4);
            uint32_t h0, l0, h1, l1;
            split2(v.x, v.y, h0, l0);
            split2(v.z, v.w, h1, l1);
            *reinterpret_cast<uint2*>(&AsH[r][c4 >> 1]) = make_uint2(h0, h1);
            *reinterpret_cast<uint2*>(&AsL[r][c4 >> 1]) = make_uint2(l0, l1);
        }
        // B tile: 64x32 floats = 512 float4
#pragma unroll
        for (int j = 0; j < 2; j++) {
            int idx = tid + j * 256;
            int r = idx >> 3, c4 = (idx & 7) << 2;
            float4 v = *reinterpret_cast<const float4*>(B + (size_t)r * ldb + kc + c4);
            uint32_t h0, l0, h1, l1;
            split2(v.x, v.y, h0, l0);
            split2(v.z, v.w, h1, l1);
            *reinterpret_cast<uint2*>(&BsH[r][c4 >> 1]) = make_uint2(h0, h1);
            *reinterpret_cast<uint2*>(&BsL[r][c4 >> 1]) = make_uint2(l0, l1);
        }
        __syncthreads();
#pragma unroll
        for (int ks = 0; ks < 2; ks++) {
            const int ar = wid * 16 + g;
            const int wi = ks * 8 + q;
            uint32_t a0h = AsH[ar][wi],     a1h = AsH[ar + 8][wi];
            uint32_t a2h = AsH[ar][wi + 4], a3h = AsH[ar + 8][wi + 4];
            uint32_t a0l = AsL[ar][wi],     a1l = AsL[ar + 8][wi];
            uint32_t a2l = AsL[ar][wi + 4], a3l = AsL[ar + 8][wi + 4];
#pragma unroll
            for (int nt = 0; nt < 8; nt++) {
                const int br = nt * 8 + g;
                uint32_t b0h = BsH[br][wi], b1h = BsH[br][wi + 4];
                uint32_t b0l = BsL[br][wi], b1l = BsL[br][wi + 4];
                mma16816(acc[nt], a0h, a1h, a2h, a3h, b0h, b1h);
                mma16816(acc[nt], a0h, a1h, a2h, a3h, b0l, b1l);
                mma16816(acc[nt], a0l, a1l, a2l, a3l, b0h, b1h);
            }
        }
        __syncthreads();
    }
    const int r0 = wid * 16 + g;
#pragma unroll
    for (int nt = 0; nt < 8; nt++) {
        int cx = nt * 8 + 2 * q;
        *reinterpret_cast<float2*>(C + (size_t)r0 * ldc + cx) =
            make_float2(acc[nt][0], acc[nt][1]);
        *reinterpret_cast<float2*>(C + (size_t)(r0 + 8) * ldc + cx) =
            make_float2(acc[nt][2], acc[nt][3]);
    }
}

// ---------------- stage 1: QKV projections --------------------------------
__global__ void __launch_bounds__(256) qkv_kernel(const float* __restrict__ X,
                                                  const float* __restrict__ WQ,
                                                  const float* __restrict__ WK,
                                                  const float* __restrict__ WV) {
    const int bm = blockIdx.x, h = blockIdx.y, z = blockIdx.z;
    const float* W = (z == 0) ? WQ : (z == 1) ? WK : WV;
    float* Cbase   = (z == 0) ? g_Q : (z == 1) ? g_K : g_V;
    gemm_core(X + ((size_t)h * NSEQ + (size_t)bm * 128) * FIN, FIN,
              W + (size_t)h * HD * FIN, FIN,
              Cbase + ((size_t)h * NSEQ + (size_t)bm * 128) * HD, HD);
}

// ---------------- stage 3: output projection ------------------------------
__global__ void __launch_bounds__(256) out_kernel(const float* __restrict__ WO,
                                                  float* __restrict__ out) {
    const int bm = blockIdx.x, bn = blockIdx.y;
    gemm_core(g_Hcat + (size_t)bm * 128 * FIN, FIN,
              WO + (size_t)bn * HD * FIN, FIN,
              out + (size_t)bm * 128 * FIN + (size_t)bn * HD, FIN);
}

// ---------------- stage 2: flash attention --------------------------------
// BM=128 rows per CTA, BN=64 cols per iteration, 8 warps x 16 full rows.
// dyn smem layout (uint32 words): QH[128][36], QL[128][36], KH[64][36], KL[64][36],
//                                 VTH[64][36], VTL[64][36]   (stride 36 words = 72 bf16)
#define SM_QH  0
#define SM_QL  4608
#define SM_KH  9216
#define SM_KL  11520
#define SM_VTH 13824
#define SM_VTL 16128
#define SMEM_WORDS 18432   // 73728 bytes

__global__ void __launch_bounds__(256) attn_kernel(const int* __restrict__ mask) {
    extern __shared__ __align__(16) uint32_t sm[];
    uint32_t* QH = sm + SM_QH;
    uint32_t* QL = sm + SM_QL;
    uint32_t* KH = sm + SM_KH;
    uint32_t* KL = sm + SM_KL;
    uint32_t* VTHu = sm + SM_VTH;
    uint32_t* VTLu = sm + SM_VTL;
    __nv_bfloat16* VTH = reinterpret_cast<__nv_bfloat16*>(VTHu);
    __nv_bfloat16* VTL = reinterpret_cast<__nv_bfloat16*>(VTLu);

    const int tid = threadIdx.x, wid = tid >> 5, lane = tid & 31;
    const int g = lane >> 2, q = lane & 3;
    const int bm = blockIdx.x, h = blockIdx.y;

    const float* Qt = g_Q + ((size_t)h * NSEQ + (size_t)bm * 128) * HD;
    const float* Kg = g_K + (size_t)h * NSEQ * HD;
    const float* Vg = g_V + (size_t)h * NSEQ * HD;
    const int* mbase = mask + ((size_t)h * NSEQ + (size_t)bm * 128) * NSEQ;

    // ---- load Q tile (128x64) into smem, split hi/lo
#pragma unroll
    for (int j = 0; j < 8; j++) {
        int idx = tid + j * 256;               // 0..2047 float4
        int r = idx >> 4, c4 = (idx & 15) << 2;
        float4 v = *reinterpret_cast<const float4*>(Qt + (size_t)r * HD + c4);
        uint32_t h0, l0, h1, l1;
        split2(v.x, v.y, h0, l0);
        split2(v.z, v.w, h1, l1);
        *reinterpret_cast<uint2*>(&QH[r * 36 + (c4 >> 1)]) = make_uint2(h0, h1);
        *reinterpret_cast<uint2*>(&QL[r * 36 + (c4 >> 1)]) = make_uint2(l0, l1);
    }

    float O[8][4];
#pragma unroll
    for (int i = 0; i < 8; i++)
#pragma unroll
        for (int j = 0; j < 4; j++) O[i][j] = 0.f;
    const float NEGINF = __int_as_float(0xff800000);
    float m0 = NEGINF, m1 = NEGINF, l0s = 0.f, l1s = 0.f;

    for (int nb = 0; nb < NSEQ / 64; nb++) {
        __syncthreads();   // previous iteration's smem reads done
        // ---- fill K tile (64x64) and V^T tile
#pragma unroll
        for (int j = 0; j < 4; j++) {
            int idx = tid + j * 256;           // 0..1023 float4
            int r = idx >> 4, c4 = (idx & 15) << 2;
            float4 v = *reinterpret_cast<const float4*>(Kg + (size_t)(nb * 64 + r) * HD + c4);
            uint32_t h0, l0, h1, l1;
            split2(v.x, v.y, h0, l0);
            split2(v.z, v.w, h1, l1);
            *reinterpret_cast<uint2*>(&KH[r * 36 + (c4 >> 1)]) = make_uint2(h0, h1);
            *reinterpret_cast<uint2*>(&KL[r * 36 + (c4 >> 1)]) = make_uint2(l0, l1);

            float4 w = *reinterpret_cast<const float4*>(Vg + (size_t)(nb * 64 + r) * HD + c4);
            float e0 = w.x, e1 = w.y, e2 = w.z, e3 = w.w;
            float eh;
            eh = __bfloat162float(__float2bfloat16_rn(e0));
            VTH[(c4 + 0) * 72 + r] = __float2bfloat16_rn(e0);
            VTL[(c4 + 0) * 72 + r] = __float2bfloat16_rn(e0 - eh);
            eh = __bfloat162float(__float2bfloat16_rn(e1));
            VTH[(c4 + 1) * 72 + r] = __float2bfloat16_rn(e1);
            VTL[(c4 + 1) * 72 + r] = __float2bfloat16_rn(e1 - eh);
            eh = __bfloat162float(__float2bfloat16_rn(e2));
            VTH[(c4 + 2) * 72 + r] = __float2bfloat16_rn(e2);
            VTL[(c4 + 2) * 72 + r] = __float2bfloat16_rn(e2 - eh);
            eh = __bfloat162float(__float2bfloat16_rn(e3));
            VTH[(c4 + 3) * 72 + r] = __float2bfloat16_rn(e3);
            VTL[(c4 + 3) * 72 + r] = __float2bfloat16_rn(e3 - eh);
        }
        __syncthreads();

        // ---- S = Q * K^T  (warp rows 16*wid .. +15, all 64 cols)
        float S[8][4];
#pragma unroll
        for (int i = 0; i < 8; i++)
#pragma unroll
            for (int j = 0; j < 4; j++) S[i][j] = 0.f;
#pragma unroll
        for (int ks = 0; ks < 4; ks++) {
            const int ar = wid * 16 + g;
            const int wi = ks * 8 + q;
            uint32_t a0h = QH[ar * 36 + wi],       a1h = QH[(ar + 8) * 36 + wi];
            uint32_t a2h = QH[ar * 36 + wi + 4],   a3h = QH[(ar + 8) * 36 + wi + 4];
            uint32_t a0l = QL[ar * 36 + wi],       a1l = QL[(ar + 8) * 36 + wi];
            uint32_t a2l = QL[ar * 36 + wi + 4],   a3l = QL[(ar + 8) * 36 + wi + 4];
#pragma unroll
            for (int nt = 0; nt < 8; nt++) {
                const int br = nt * 8 + g;
                uint32_t b0h = KH[br * 36 + wi], b1h = KH[br * 36 + wi + 4];
                uint32_t b0l = KL[br * 36 + wi], b1l = KL[br * 36 + wi + 4];
                mma16816(S[nt], a0h, a1h, a2h, a3h, b0h, b1h);
                mma16816(S[nt], a0h, a1h, a2h, a3h, b0l, b1l);
                mma16816(S[nt], a0l, a1l, a2l, a3l, b0h, b1h);
            }
        }

        // ---- scale + mask (direct from gmem)
        const int* mr0 = mbase + (size_t)(wid * 16 + g) * NSEQ + nb * 64;
        const int* mr1 = mr0 + 8 * NSEQ;
#pragma unroll
        for (int nt = 0; nt < 8; nt++) {
            int2 ma = *reinterpret_cast<const int2*>(mr0 + nt * 8 + 2 * q);
            int2 mb = *reinterpret_cast<const int2*>(mr1 + nt * 8 + 2 * q);
            S[nt][0] = ma.x ? S[nt][0] * 0.125f : NEG_BIG;
            S[nt][1] = ma.y ? S[nt][1] * 0.125f : NEG_BIG;
            S[nt][2] = mb.x ? S[nt][2] * 0.125f : NEG_BIG;
            S[nt][3] = mb.y ? S[nt][3] * 0.125f : NEG_BIG;
        }

        // ---- online softmax (each quad of lanes owns one row pair)
        float mx0 = S[0][0], mx1 = S[0][2];
#pragma unroll
        for (int nt = 0; nt < 8; nt++) {
            mx0 = fmaxf(mx0, fmaxf(S[nt][0], S[nt][1]));
            mx1 = fmaxf(mx1, fmaxf(S[nt][2], S[nt][3]));
        }
        mx0 = fmaxf(mx0, __shfl_xor_sync(0xffffffffu, mx0, 1));
        mx0 = fmaxf(mx0, __shfl_xor_sync(0xffffffffu, mx0, 2));
        mx1 = fmaxf(mx1, __shfl_xor_sync(0xffffffffu, mx1, 1));
        mx1 = fmaxf(mx1, __shfl_xor_sync(0xffffffffu, mx1, 2));

        float mn0 = fmaxf(m0, mx0), mn1 = fmaxf(m1, mx1);
        float al0 = __expf(m0 - mn0), al1 = __expf(m1 - mn1);
        m0 = mn0;
        m1 = mn1;

        float rs0 = 0.f, rs1 = 0.f;
#pragma unroll
        for (int nt = 0; nt < 8; nt++) {
            S[nt][0] = __expf(S[nt][0] - m0);
            S[nt][1] = __expf(S[nt][1] - m0);
            S[nt][2] = __expf(S[nt][2] - m1);
            S[nt][3] = __expf(S[nt][3] - m1);
            rs0 += S[nt][0] + S[nt][1];
            rs1 += S[nt][2] + S[nt][3];
        }
        rs0 += __shfl_xor_sync(0xffffffffu, rs0, 1);
        rs0 += __shfl_xor_sync(0xffffffffu, rs0, 2);
        rs1 += __shfl_xor_sync(0xffffffffu, rs1, 1);
        rs1 += __shfl_xor_sync(0xffffffffu, rs1, 2);
        l0s = l0s * al0 + rs0;
        l1s = l1s * al1 + rs1;
#pragma unroll
        for (int nt = 0; nt < 8; nt++) {
            O[nt][0] *= al0;
            O[nt][1] *= al0;
            O[nt][2] *= al1;
            O[nt][3] *= al1;
        }

        // ---- O += P * V   (P's C-layout == A-layout for m16n8k16)
#pragma unroll
        for (int ks = 0; ks < 4; ks++) {
            uint32_t a0h, a0l, a1h, a1l, a2h, a2l, a3h, a3l;
            split2(S[2 * ks][0],     S[2 * ks][1],     a0h, a0l);
            split2(S[2 * ks][2],     S[2 * ks][3],     a1h, a1l);
            split2(S[2 * ks + 1][0], S[2 * ks + 1][1], a2h, a2l);
            split2(S[2 * ks + 1][2], S[2 * ks + 1][3], a3h, a3l);
            const int wi = ks * 8 + q;
#pragma unroll
            for (int nt = 0; nt < 8; nt++) {
                const int vr = nt * 8 + g;
                uint32_t b0h = VTHu[vr * 36 + wi], b1h = VTHu[vr * 36 + wi + 4];
                uint32_t b0l = VTLu[vr * 36 + wi], b1l = VTLu[vr * 36 + wi + 4];
                mma16816(O[nt], a0h, a1h, a2h, a3h, b0h, b1h);
                mma16816(O[nt], a0h, a1h, a2h, a3h, b0l, b1l);
                mma16816(O[nt], a0l, a1l, a2l, a3l, b0h, b1h);
            }
        }
    }

    // ---- epilogue: normalize and scatter to Hcat[n][h*64+d]
    float inv0 = 1.0f / l0s, inv1 = 1.0f / l1s;
    const int r0 = bm * 128 + wid * 16 + g;
#pragma unroll
    for (int nt = 0; nt < 8; nt++) {
        int cx = h * HD + nt * 8 + 2 * q;
        *reinterpret_cast<float2*>(g_Hcat + (size_t)r0 * FIN + cx) =
            make_float2(O[nt][0] * inv0, O[nt][1] * inv0);
        *reinterpret_cast<float2*>(g_Hcat + (size_t)(r0 + 8) * FIN + cx) =
            make_float2(O[nt][2] * inv1, O[nt][3] * inv1);
    }
}

// ---------------- launcher --------------------------------------------------
extern "C" void kernel_launch(void* const* d_in, const int* in_sizes, int n_in,
                              void* d_out, int out_size) {
    const float* X   = (const float*)d_in[0];
    const int*   msk = (const int*)d_in[1];
    const float* WQ  = (const float*)d_in[2];
    const float* WK  = (const float*)d_in[3];
    const float* WV  = (const float*)d_in[4];
    const float* WO  = (const float*)d_in[5];
    float* out = (float*)d_out;

    cudaFuncSetAttribute(attn_kernel, cudaFuncAttributeMaxDynamicSharedMemorySize,
                         SMEM_WORDS * 4);

    qkv_kernel<<<dim3(NSEQ / 128, HNUM, 3), 256>>>(X, WQ, WK, WV);
    attn_kernel<<<dim3(NSEQ / 128, HNUM), 256, SMEM_WORDS * 4>>>(msk);
    out_kernel<<<dim3(NSEQ / 128, FIN / HD), 256>>>(WO, out);
}

// round 2
// speedup vs baseline: 1.1083x; 1.1083x over previous
#include <cuda_runtime.h>
#include <cuda_bf16.h>
#include <cstdint>

#define HNUM 8
#define NSEQ 4096
#define FIN  512
#define HD   64

// ---------------- scratch (static device globals; no allocations) ----------
// pre-split inputs (bf16 hi/lo packed as bf16x2 words)
__device__ uint32_t g_XH[HNUM * NSEQ * (FIN / 2)];
__device__ uint32_t g_XL[HNUM * NSEQ * (FIN / 2)];
__device__ uint32_t g_WH[3 * HNUM * HD * (FIN / 2)];
__device__ uint32_t g_WL[3 * HNUM * HD * (FIN / 2)];
__device__ uint32_t g_WOH[FIN * (FIN / 2)];
__device__ uint32_t g_WOL[FIN * (FIN / 2)];
// Q/K packed split [h][n][32 words]
__device__ uint32_t g_QH[HNUM * NSEQ * (HD / 2)];
__device__ uint32_t g_QL[HNUM * NSEQ * (HD / 2)];
__device__ uint32_t g_KH[HNUM * NSEQ * (HD / 2)];
__device__ uint32_t g_KL[HNUM * NSEQ * (HD / 2)];
// V transposed pre-split [h][d][n] as raw bf16
__device__ unsigned short g_VTH[HNUM * HD * NSEQ];
__device__ unsigned short g_VTL[HNUM * HD * NSEQ];
// attention output, pre-split for the out-GEMM [n][256 words]
__device__ uint32_t g_HH[NSEQ * (FIN / 2)];
__device__ uint32_t g_HL[NSEQ * (FIN / 2)];

// ---------------- helpers --------------------------------------------------
__device__ __forceinline__ uint32_t pack_bf16x2(float lo_elem, float hi_elem) {
    return (uint32_t)__bfloat16_as_ushort(__float2bfloat16_rn(lo_elem)) |
           ((uint32_t)__bfloat16_as_ushort(__float2bfloat16_rn(hi_elem)) << 16);
}

__device__ __forceinline__ void split2(float a, float b, uint32_t& hi, uint32_t& lo) {
    float ah = __bfloat162float(__float2bfloat16_rn(a));
    float bh = __bfloat162float(__float2bfloat16_rn(b));
    hi = pack_bf16x2(a, b);
    lo = pack_bf16x2(a - ah, b - bh);
}

__device__ __forceinline__ void mma16816(float* c,
                                         uint32_t a0, uint32_t a1, uint32_t a2, uint32_t a3,
                                         uint32_t b0, uint32_t b1) {
    asm volatile(
        "mma.sync.aligned.m16n8k16.row.col.f32.bf16.bf16.f32 "
        "{%0,%1,%2,%3},{%4,%5,%6,%7},{%8,%9},{%0,%1,%2,%3};\n"
        : "+f"(c[0]), "+f"(c[1]), "+f"(c[2]), "+f"(c[3])
        : "r"(a0), "r"(a1), "r"(a2), "r"(a3), "r"(b0), "r"(b1));
}

__device__ __forceinline__ void cp16(uint32_t dst, const void* src) {
    asm volatile("cp.async.cg.shared.global [%0], [%1], 16;" :: "r"(dst), "l"(src));
}
__device__ __forceinline__ void cp_commit() {
    asm volatile("cp.async.commit_group;" ::: "memory");
}
__device__ __forceinline__ void cp_wait1() {
    asm volatile("cp.async.wait_group 1;" ::: "memory");
}
__device__ __forceinline__ void cp_wait0() {
    asm volatile("cp.async.wait_group 0;" ::: "memory");
}

#define NEG_BIG (-1.0e30f)

// ---------------- split kernel: fp32 -> packed bf16 hi/lo -------------------
__global__ void __launch_bounds__(256) split_kernel(const float* __restrict__ src,
                                                    int which, int nquads) {
    uint32_t* dH;
    uint32_t* dL;
    switch (which) {
        case 0: dH = g_XH;               dL = g_XL;               break;
        case 1: dH = g_WH;               dL = g_WL;               break;
        case 2: dH = g_WH + 131072;      dL = g_WL + 131072;      break;
        case 3: dH = g_WH + 262144;      dL = g_WL + 262144;      break;
        default: dH = g_WOH;             dL = g_WOL;              break;
    }
    for (int i = blockIdx.x * blockDim.x + threadIdx.x; i < nquads;
         i += gridDim.x * blockDim.x) {
        float4 v = reinterpret_cast<const float4*>(src)[i];
        uint32_t h0, l0, h1, l1;
        split2(v.x, v.y, h0, l0);
        split2(v.z, v.w, h1, l1);
        reinterpret_cast<uint2*>(dH)[i] = make_uint2(h0, h1);
        reinterpret_cast<uint2*>(dL)[i] = make_uint2(l0, l1);
    }
}

// ---------------- GEMM core: acc[128x64] += A[128,512] * B[64,512]^T --------
// operands pre-split in global (row stride 256 words). 256 threads.
__device__ __forceinline__ void gemm_accum(const uint32_t* __restrict__ AHg,
                                           const uint32_t* __restrict__ ALg,
                                           const uint32_t* __restrict__ BHg,
                                           const uint32_t* __restrict__ BLg,
                                           float acc[8][4]) {
    __shared__ __align__(16) uint32_t AsH[128][36];
    __shared__ __align__(16) uint32_t AsL[128][36];
    __shared__ __align__(16) uint32_t BsH[64][36];
    __shared__ __align__(16) uint32_t BsL[64][36];

    const int tid = threadIdx.x;
    const int wid = tid >> 5, lane = tid & 31;
    const int g = lane >> 2, q = lane & 3;

    for (int kc = 0; kc < 256; kc += 32) {   // 32 words = 64 elems per iter
#pragma unroll
        for (int j = 0; j < 4; j++) {
            int idx = tid + j * 256;
            int r = idx >> 3, c = (idx & 7) << 2;
            *reinterpret_cast<uint4*>(&AsH[r][c]) =
                *reinterpret_cast<const uint4*>(AHg + (size_t)r * 256 + kc + c);
            *reinterpret_cast<uint4*>(&AsL[r][c]) =
                *reinterpret_cast<const uint4*>(ALg + (size_t)r * 256 + kc + c);
        }
#pragma unroll
        for (int j = 0; j < 2; j++) {
            int idx = tid + j * 256;
            int r = idx >> 3, c = (idx & 7) << 2;
            *reinterpret_cast<uint4*>(&BsH[r][c]) =
                *reinterpret_cast<const uint4*>(BHg + (size_t)r * 256 + kc + c);
            *reinterpret_cast<uint4*>(&BsL[r][c]) =
                *reinterpret_cast<const uint4*>(BLg + (size_t)r * 256 + kc + c);
        }
        __syncthreads();
#pragma unroll
        for (int ks = 0; ks < 4; ks++) {
            const int ar = wid * 16 + g;
            const int wi = ks * 8 + q;
            uint32_t a0h = AsH[ar][wi],     a1h = AsH[ar + 8][wi];
            uint32_t a2h = AsH[ar][wi + 4], a3h = AsH[ar + 8][wi + 4];
            uint32_t a0l = AsL[ar][wi],     a1l = AsL[ar + 8][wi];
            uint32_t a2l = AsL[ar][wi + 4], a3l = AsL[ar + 8][wi + 4];
#pragma unroll
            for (int nt = 0; nt < 8; nt++) {
                const int br = nt * 8 + g;
                uint32_t b0h = BsH[br][wi], b1h = BsH[br][wi + 4];
                uint32_t b0l = BsL[br][wi], b1l = BsL[br][wi + 4];
                mma16816(acc[nt], a0h, a1h, a2h, a3h, b0h, b1h);
                mma16816(acc[nt], a0h, a1h, a2h, a3h, b0l, b1l);
                mma16816(acc[nt], a0l, a1l, a2l, a3l, b0h, b1h);
            }
        }
        __syncthreads();
    }
}

// ---------------- stage 1: QKV projections --------------------------------
__global__ void __launch_bounds__(256) qkv_kernel() {
    const int bm = blockIdx.x, h = blockIdx.y, z = blockIdx.z;
    const int tid = threadIdx.x;
    const int wid = tid >> 5, lane = tid & 31;
    const int g = lane >> 2, q = lane & 3;

    float acc[8][4];
#pragma unroll
    for (int i = 0; i < 8; i++)
#pragma unroll
        for (int j = 0; j < 4; j++) acc[i][j] = 0.f;

    const uint32_t* AH = g_XH + (size_t)(h * NSEQ + bm * 128) * 256;
    const uint32_t* AL = g_XL + (size_t)(h * NSEQ + bm * 128) * 256;
    const uint32_t* BH = g_WH + (size_t)((z * HNUM + h) * HD) * 256;
    const uint32_t* BL = g_WL + (size_t)((z * HNUM + h) * HD) * 256;
    gemm_accum(AH, AL, BH, BL, acc);

    const int r0 = wid * 16 + g;
    if (z < 2) {
        uint32_t* dH = (z == 0) ? g_QH : g_KH;
        uint32_t* dL = (z == 0) ? g_QL : g_KL;
        const size_t rb0 = (size_t)(h * NSEQ + bm * 128 + r0) * 32;
        const size_t rb1 = rb0 + 8 * 32;
#pragma unroll
        for (int nt = 0; nt < 8; nt++) {
            int w = nt * 4 + q;
            uint32_t H, L;
            split2(acc[nt][0], acc[nt][1], H, L);
            dH[rb0 + w] = H; dL[rb0 + w] = L;
            split2(acc[nt][2], acc[nt][3], H, L);
            dH[rb1 + w] = H; dL[rb1 + w] = L;
        }
    } else {
        // V: write transposed pre-split [h][d][n]
        const int n0 = bm * 128 + r0;
#pragma unroll
        for (int nt = 0; nt < 8; nt++) {
            int cx = nt * 8 + 2 * q;
#pragma unroll
            for (int e = 0; e < 2; e++) {
                size_t b0 = (size_t)(h * HD + cx + e) * NSEQ;
                float v0 = acc[nt][e], v1 = acc[nt][2 + e];
                float h0 = __bfloat162float(__float2bfloat16_rn(v0));
                float h1 = __bfloat162float(__float2bfloat16_rn(v1));
                g_VTH[b0 + n0]     = __bfloat16_as_ushort(__float2bfloat16_rn(v0));
                g_VTL[b0 + n0]     = __bfloat16_as_ushort(__float2bfloat16_rn(v0 - h0));
                g_VTH[b0 + n0 + 8] = __bfloat16_as_ushort(__float2bfloat16_rn(v1));
                g_VTL[b0 + n0 + 8] = __bfloat16_as_ushort(__float2bfloat16_rn(v1 - h1));
            }
        }
    }
}

// ---------------- stage 3: output projection ------------------------------
__global__ void __launch_bounds__(256) out_kernel(float* __restrict__ out) {
    const int bm = blockIdx.x, bn = blockIdx.y;
    const int tid = threadIdx.x;
    const int wid = tid >> 5, lane = tid & 31;
    const int g = lane >> 2, q = lane & 3;

    float acc[8][4];
#pragma unroll
    for (int i = 0; i < 8; i++)
#pragma unroll
        for (int j = 0; j < 4; j++) acc[i][j] = 0.f;

    gemm_accum(g_HH + (size_t)bm * 128 * 256, g_HL + (size_t)bm * 128 * 256,
               g_WOH + (size_t)bn * HD * 256, g_WOL + (size_t)bn * HD * 256, acc);

    const int r0 = wid * 16 + g;
#pragma unroll
    for (int nt = 0; nt < 8; nt++) {
        int cx = bn * HD + nt * 8 + 2 * q;
        *reinterpret_cast<float2*>(out + (size_t)(bm * 128 + r0) * FIN + cx) =
            make_float2(acc[nt][0], acc[nt][1]);
        *reinterpret_cast<float2*>(out + (size_t)(bm * 128 + r0 + 8) * FIN + cx) =
            make_float2(acc[nt][2], acc[nt][3]);
    }
}

// ---------------- stage 2: flash attention --------------------------------
// double-buffered smem: per buffer 9216 words: KH@0, KL@2304, VTH@4608, VTL@6912
// row stride 36 words (32 data + 4 pad)
#define ATTN_BUF_WORDS 9216
#define ATTN_SMEM_BYTES (2 * ATTN_BUF_WORDS * 4)

__device__ __forceinline__ void attn_issue(int h, int nb, uint32_t sbase) {
    const int tid = threadIdx.x;
#pragma unroll
    for (int j = 0; j < 2; j++) {
        int chunk = tid + j * 256;
        int r = chunk >> 3, c = chunk & 7;
        const uint32_t* sKH = g_KH + (size_t)(h * NSEQ + nb * 64 + r) * 32 + c * 4;
        const uint32_t* sKL = g_KL + (size_t)(h * NSEQ + nb * 64 + r) * 32 + c * 4;
        const unsigned short* sVH = g_VTH + (size_t)(h * HD + r) * NSEQ + nb * 64 + c * 8;
        const unsigned short* sVL = g_VTL + (size_t)(h * HD + r) * NSEQ + nb * 64 + c * 8;
        uint32_t d = sbase + (uint32_t)(r * 36 + c * 4) * 4;
        cp16(d, sKH);
        cp16(d + 2304 * 4, sKL);
        cp16(d + 4608 * 4, sVH);
        cp16(d + 6912 * 4, sVL);
    }
}

__global__ void __launch_bounds__(256) attn_kernel(const int* __restrict__ mask) {
    extern __shared__ __align__(16) uint32_t sm[];
    const uint32_t smem_u32 = (uint32_t)__cvta_generic_to_shared(sm);

    const int tid = threadIdx.x, wid = tid >> 5, lane = tid & 31;
    const int g = lane >> 2, q = lane & 3;
    const int bm = blockIdx.x, h = blockIdx.y;

    // ---- Q fragments into registers (once per CTA)
    uint32_t qh[4][4], ql[4][4];
    {
        const size_t rb0 = (size_t)(h * NSEQ + bm * 128 + wid * 16 + g) * 32;
        const size_t rb1 = rb0 + 8 * 32;
#pragma unroll
        for (int ks = 0; ks < 4; ks++) {
            int wi = ks * 8 + q;
            qh[ks][0] = g_QH[rb0 + wi];
            qh[ks][1] = g_QH[rb1 + wi];
            qh[ks][2] = g_QH[rb0 + wi + 4];
            qh[ks][3] = g_QH[rb1 + wi + 4];
            ql[ks][0] = g_QL[rb0 + wi];
            ql[ks][1] = g_QL[rb1 + wi];
            ql[ks][2] = g_QL[rb0 + wi + 4];
            ql[ks][3] = g_QL[rb1 + wi + 4];
        }
    }

    const int* mbase = mask + ((size_t)h * NSEQ + (size_t)bm * 128) * NSEQ;

    float O[8][4];
#pragma unroll
    for (int i = 0; i < 8; i++)
#pragma unroll
        for (int j = 0; j < 4; j++) O[i][j] = 0.f;
    const float NEGINF = __int_as_float(0xff800000);
    float m0 = NEGINF, m1 = NEGINF, l0s = 0.f, l1s = 0.f;

    attn_issue(h, 0, smem_u32);
    cp_commit();

    for (int nb = 0; nb < NSEQ / 64; nb++) {
        __syncthreads();   // reads of the buffer we are about to overwrite are done
        if (nb + 1 < NSEQ / 64) {
            attn_issue(h, nb + 1, smem_u32 + ((nb + 1) & 1) * ATTN_BUF_WORDS * 4);
            cp_commit();
            cp_wait1();
        } else {
            cp_wait0();
        }
        __syncthreads();

        const uint32_t* KH = sm + (nb & 1) * ATTN_BUF_WORDS;
        const uint32_t* KL = KH + 2304;
        const uint32_t* VTH = KH + 4608;
        const uint32_t* VTL = KH + 6912;

        // ---- S = Q * K^T
        float S[8][4];
#pragma unroll
        for (int i = 0; i < 8; i++)
#pragma unroll
            for (int j = 0; j < 4; j++) S[i][j] = 0.f;
#pragma unroll
        for (int ks = 0; ks < 4; ks++) {
            const int wi = ks * 8 + q;
#pragma unroll
            for (int nt = 0; nt < 8; nt++) {
                const int br = nt * 8 + g;
                uint32_t b0h = KH[br * 36 + wi], b1h = KH[br * 36 + wi + 4];
                uint32_t b0l = KL[br * 36 + wi], b1l = KL[br * 36 + wi + 4];
                mma16816(S[nt], qh[ks][0], qh[ks][1], qh[ks][2], qh[ks][3], b0h, b1h);
                mma16816(S[nt], qh[ks][0], qh[ks][1], qh[ks][2], qh[ks][3], b0l, b1l);
                mma16816(S[nt], ql[ks][0], ql[ks][1], ql[ks][2], ql[ks][3], b0h, b1h);
            }
        }

        // ---- scale + mask (direct from gmem)
        const int* mr0 = mbase + (size_t)(wid * 16 + g) * NSEQ + nb * 64;
        const int* mr1 = mr0 + 8 * NSEQ;
#pragma unroll
        for (int nt = 0; nt < 8; nt++) {
            int2 ma = *reinterpret_cast<const int2*>(mr0 + nt * 8 + 2 * q);
            int2 mb = *reinterpret_cast<const int2*>(mr1 + nt * 8 + 2 * q);
            S[nt][0] = ma.x ? S[nt][0] * 0.125f : NEG_BIG;
            S[nt][1] = ma.y ? S[nt][1] * 0.125f : NEG_BIG;
            S[nt][2] = mb.x ? S[nt][2] * 0.125f : NEG_BIG;
            S[nt][3] = mb.y ? S[nt][3] * 0.125f : NEG_BIG;
        }

        // ---- online softmax
        float mx0 = S[0][0], mx1 = S[0][2];
#pragma unroll
        for (int nt = 0; nt < 8; nt++) {
            mx0 = fmaxf(mx0, fmaxf(S[nt][0], S[nt][1]));
            mx1 = fmaxf(mx1, fmaxf(S[nt][2], S[nt][3]));
        }
        mx0 = fmaxf(mx0, __shfl_xor_sync(0xffffffffu, mx0, 1));
        mx0 = fmaxf(mx0, __shfl_xor_sync(0xffffffffu, mx0, 2));
        mx1 = fmaxf(mx1, __shfl_xor_sync(0xffffffffu, mx1, 1));
        mx1 = fmaxf(mx1, __shfl_xor_sync(0xffffffffu, mx1, 2));

        float mn0 = fmaxf(m0, mx0), mn1 = fmaxf(m1, mx1);
        float al0 = __expf(m0 - mn0), al1 = __expf(m1 - mn1);
        m0 = mn0;
        m1 = mn1;

        float rs0 = 0.f, rs1 = 0.f;
#pragma unroll
        for (int nt = 0; nt < 8; nt++) {
            S[nt][0] = __expf(S[nt][0] - m0);
            S[nt][1] = __expf(S[nt][1] - m0);
            S[nt][2] = __expf(S[nt][2] - m1);
            S[nt][3] = __expf(S[nt][3] - m1);
            rs0 += S[nt][0] + S[nt][1];
            rs1 += S[nt][2] + S[nt][3];
        }
        rs0 += __shfl_xor_sync(0xffffffffu, rs0, 1);
        rs0 += __shfl_xor_sync(0xffffffffu, rs0, 2);
        rs1 += __shfl_xor_sync(0xffffffffu, rs1, 1);
        rs1 += __shfl_xor_sync(0xffffffffu, rs1, 2);
        l0s = l0s * al0 + rs0;
        l1s = l1s * al1 + rs1;
#pragma unroll
        for (int nt = 0; nt < 8; nt++) {
            O[nt][0] *= al0;
            O[nt][1] *= al0;
            O[nt][2] *= al1;
            O[nt][3] *= al1;
        }

        // ---- O += P * V
#pragma unroll
        for (int ks = 0; ks < 4; ks++) {
            uint32_t a0h, a0l, a1h, a1l, a2h, a2l, a3h, a3l;
            split2(S[2 * ks][0],     S[2 * ks][1],     a0h, a0l);
            split2(S[2 * ks][2],     S[2 * ks][3],     a1h, a1l);
            split2(S[2 * ks + 1][0], S[2 * ks + 1][1], a2h, a2l);
            split2(S[2 * ks + 1][2], S[2 * ks + 1][3], a3h, a3l);
            const int wi = ks * 8 + q;
#pragma unroll
            for (int nt = 0; nt < 8; nt++) {
                const int vr = nt * 8 + g;
                uint32_t b0h = VTH[vr * 36 + wi], b1h = VTH[vr * 36 + wi + 4];
                uint32_t b0l = VTL[vr * 36 + wi], b1l = VTL[vr * 36 + wi + 4];
                mma16816(O[nt], a0h, a1h, a2h, a3h, b0h, b1h);
                mma16816(O[nt], a0h, a1h, a2h, a3h, b0l, b1l);
                mma16816(O[nt], a0l, a1l, a2l, a3l, b0h, b1h);
            }
        }
    }

    // ---- epilogue: normalize, split, write packed Hcat
    float inv0 = 1.0f / l0s, inv1 = 1.0f / l1s;
    const size_t r0 = (size_t)(bm * 128 + wid * 16 + g);
#pragma unroll
    for (int nt = 0; nt < 8; nt++) {
        int w = h * 32 + nt * 4 + q;
        uint32_t H, L;
        split2(O[nt][0] * inv0, O[nt][1] * inv0, H, L);
        g_HH[r0 * 256 + w] = H;
        g_HL[r0 * 256 + w] = L;
        split2(O[nt][2] * inv1, O[nt][3] * inv1, H, L);
        g_HH[(r0 + 8) * 256 + w] = H;
        g_HL[(r0 + 8) * 256 + w] = L;
    }
}

// ---------------- launcher --------------------------------------------------
extern "C" void kernel_launch(void* const* d_in, const int* in_sizes, int n_in,
                              void* d_out, int out_size) {
    const float* X   = (const float*)d_in[0];
    const int*   msk = (const int*)d_in[1];
    const float* WQ  = (const float*)d_in[2];
    const float* WK  = (const float*)d_in[3];
    const float* WV  = (const float*)d_in[4];
    const float* WO  = (const float*)d_in[5];
    float* out = (float*)d_out;

    cudaFuncSetAttribute(attn_kernel, cudaFuncAttributeMaxDynamicSharedMemorySize,
                         ATTN_SMEM_BYTES);

    split_kernel<<<8192, 256>>>(X,  0, HNUM * NSEQ * FIN / 4);
    split_kernel<<<256,  256>>>(WQ, 1, HNUM * HD * FIN / 4);
    split_kernel<<<256,  256>>>(WK, 2, HNUM * HD * FIN / 4);
    split_kernel<<<256,  256>>>(WV, 3, HNUM * HD * FIN / 4);
    split_kernel<<<256,  256>>>(WO, 4, FIN * FIN / 4);

    qkv_kernel<<<dim3(NSEQ / 128, HNUM, 3), 256>>>();
    attn_kernel<<<dim3(NSEQ / 128, HNUM), 256, ATTN_SMEM_BYTES>>>(msk);
    out_kernel<<<dim3(NSEQ / 128, FIN / HD), 256>>>(out);
}